// round 4
// baseline (speedup 1.0000x reference)
#include <cuda_runtime.h>
#include <cstdint>

// Problem dims (fixed by the dataset)
#define B_  512
#define T_  512
#define I_  128
#define H_  512
#define C_  128
#define OT_ 128

// GEMM tile config: 32x64 output tile, K-chunks of 32, 128 threads, 4x4/thread
#define BM   32
#define BN   64
#define BK   32
#define NTHR 128

// Scratch (allocation-free rule: __device__ globals)
__device__ float g_h[2][B_ * H_];   // ping-pong hidden state, 2 MB
__device__ float g_mid[B_ * H_];    // decoder fc1 output, 1 MB
__device__ int   g_len64;           // 1 if lengths buffer is int64, 0 if int32

__global__ void zero_kernel(float* p, int n) {
    int i = blockIdx.x * blockDim.x + threadIdx.x;
    if (i < n) p[i] = 0.0f;
}

// Detect lengths dtype: values are uniform [0, 512). If the buffer is int64,
// every odd int32 word (high half) is 0. If genuinely int32, the chance all
// 32 sampled odd words are zero is (1/512)^32 ~ 0.
__global__ void detect_len_kernel(const int* p) {
    int is64 = 1;
    for (int i = 0; i < 32; i++)
        if (p[2 * i + 1] != 0) is64 = 0;
    g_len64 = is64;
}

// MODE 0: encoder step : out = mask ? tanh(A@Whh^T + x_t@Wih^T + b_ih + b_hh) : A
// MODE 1: decoder h    : out = tanh(A@Whh^T + b_ih + b_hh)
// MODE 2: fc1          : out = relu(A@fc1W^T + fc1b)
// MODE 3: fc2          : out[m, t, n] = A@fc2W^T + fc2b   (strided store to d_out)
template <int MODE>
__global__ __launch_bounds__(NTHR)
void gemm_step(const float* __restrict__ A,     // M x 512 activation
               const float* __restrict__ Wm,    // N x 512 weight (k-major)
               const float* __restrict__ x,     // MODE0: B x T x I
               const float* __restrict__ Wih,   // MODE0: H x I
               const float* __restrict__ ba,    // bias (b_ih / fc bias)
               const float* __restrict__ bb,    // b_hh (MODE0/1)
               const void* __restrict__ lengths, // MODE0 (int32 or int64)
               float* __restrict__ outp,
               int t)
{
    __shared__ __align__(16) float As[BK][BM + 4];   // [32][36]
    __shared__ __align__(16) float Bs[BK][BN + 4];   // [32][68]

    const int tid = threadIdx.x;
    const int tx  = tid & 15;     // 0..15 -> n
    const int ty  = tid >> 4;     // 0..7  -> m
    const int m0  = blockIdx.x * BM;
    const int n0  = blockIdx.y * BN;

    float acc[4][4];
#pragma unroll
    for (int i = 0; i < 4; i++)
#pragma unroll
        for (int j = 0; j < 4; j++) acc[i][j] = 0.0f;

    constexpr int NCH = H_ / BK;                       // 16 chunks over hidden K
    constexpr int NC  = (MODE == 0) ? NCH + I_ / BK : NCH;  // +4 chunks over x K

    float4 pa[2];   // A tile prefetch: 1024 floats = 256 f4 / 128 thr
    float4 pb[4];   // B tile prefetch: 2048 floats = 512 f4 / 128 thr

    auto load_chunk = [&](int c) {
        if (MODE == 0 && c >= NCH) {
            const int k0 = (c - NCH) * BK;
#pragma unroll
            for (int j = 0; j < 2; j++) {
                int f = tid + j * NTHR; int r = f >> 3; int kc = f & 7;
                pa[j] = *reinterpret_cast<const float4*>(
                    x + (size_t)(m0 + r) * (T_ * I_) + (size_t)t * I_ + k0 + kc * 4);
            }
#pragma unroll
            for (int j = 0; j < 4; j++) {
                int f = tid + j * NTHR; int r = f >> 3; int kc = f & 7;
                pb[j] = *reinterpret_cast<const float4*>(
                    Wih + (size_t)(n0 + r) * I_ + k0 + kc * 4);
            }
        } else {
            const int k0 = c * BK;
#pragma unroll
            for (int j = 0; j < 2; j++) {
                int f = tid + j * NTHR; int r = f >> 3; int kc = f & 7;
                pa[j] = *reinterpret_cast<const float4*>(
                    A + (size_t)(m0 + r) * H_ + k0 + kc * 4);
            }
#pragma unroll
            for (int j = 0; j < 4; j++) {
                int f = tid + j * NTHR; int r = f >> 3; int kc = f & 7;
                pb[j] = *reinterpret_cast<const float4*>(
                    Wm + (size_t)(n0 + r) * H_ + k0 + kc * 4);
            }
        }
    };

    auto store_chunk = [&]() {
#pragma unroll
        for (int j = 0; j < 2; j++) {
            int f = tid + j * NTHR; int r = f >> 3; int kc = f & 7;
            As[kc * 4 + 0][r] = pa[j].x;
            As[kc * 4 + 1][r] = pa[j].y;
            As[kc * 4 + 2][r] = pa[j].z;
            As[kc * 4 + 3][r] = pa[j].w;
        }
#pragma unroll
        for (int j = 0; j < 4; j++) {
            int f = tid + j * NTHR; int r = f >> 3; int kc = f & 7;
            Bs[kc * 4 + 0][r] = pb[j].x;
            Bs[kc * 4 + 1][r] = pb[j].y;
            Bs[kc * 4 + 2][r] = pb[j].z;
            Bs[kc * 4 + 3][r] = pb[j].w;
        }
    };

    load_chunk(0);
    for (int c = 0; c < NC; c++) {
        store_chunk();
        __syncthreads();
        if (c + 1 < NC) load_chunk(c + 1);  // overlap next-chunk GMEM latency
#pragma unroll
        for (int k = 0; k < BK; k++) {
            float4 a = *reinterpret_cast<const float4*>(&As[k][ty * 4]);
            float4 b = *reinterpret_cast<const float4*>(&Bs[k][tx * 4]);
            acc[0][0] += a.x * b.x; acc[0][1] += a.x * b.y; acc[0][2] += a.x * b.z; acc[0][3] += a.x * b.w;
            acc[1][0] += a.y * b.x; acc[1][1] += a.y * b.y; acc[1][2] += a.y * b.z; acc[1][3] += a.y * b.w;
            acc[2][0] += a.z * b.x; acc[2][1] += a.z * b.y; acc[2][2] += a.z * b.z; acc[2][3] += a.z * b.w;
            acc[3][0] += a.w * b.x; acc[3][1] += a.w * b.y; acc[3][2] += a.w * b.z; acc[3][3] += a.w * b.w;
        }
        __syncthreads();
    }

    // Epilogue
    const int mBase = m0 + ty * 4;
    const int nBase = n0 + tx * 4;

    float4 ba4 = *reinterpret_cast<const float4*>(ba + nBase);
    float4 bb4 = make_float4(0.f, 0.f, 0.f, 0.f);
    if constexpr (MODE == 0 || MODE == 1) {
        bb4 = *reinterpret_cast<const float4*>(bb + nBase);
    }

    [[maybe_unused]] int len64 = 0;
    if constexpr (MODE == 0) len64 = g_len64;

#pragma unroll
    for (int i = 0; i < 4; i++) {
        const int m = mBase + i;
        float v0 = acc[i][0] + ba4.x + bb4.x;
        float v1 = acc[i][1] + ba4.y + bb4.y;
        float v2 = acc[i][2] + ba4.z + bb4.z;
        float v3 = acc[i][3] + ba4.w + bb4.w;

        if constexpr (MODE == 0) {
            long long len = len64 ? ((const long long*)lengths)[m]
                                  : (long long)((const int*)lengths)[m];
            const bool act = ((long long)t < len);
            float4 o;
            if (act) {
                o.x = tanhf(v0); o.y = tanhf(v1); o.z = tanhf(v2); o.w = tanhf(v3);
            } else {
                o = *reinterpret_cast<const float4*>(A + (size_t)m * H_ + nBase);
            }
            *reinterpret_cast<float4*>(outp + (size_t)m * H_ + nBase) = o;
        } else if constexpr (MODE == 1) {
            float4 o;
            o.x = tanhf(v0); o.y = tanhf(v1); o.z = tanhf(v2); o.w = tanhf(v3);
            *reinterpret_cast<float4*>(outp + (size_t)m * H_ + nBase) = o;
        } else if constexpr (MODE == 2) {
            float4 o;
            o.x = fmaxf(v0, 0.f); o.y = fmaxf(v1, 0.f);
            o.z = fmaxf(v2, 0.f); o.w = fmaxf(v3, 0.f);
            *reinterpret_cast<float4*>(outp + (size_t)m * H_ + nBase) = o;
        } else {  // MODE == 3: out[m][t][n], row-major (B, OT, C)
            float4 o = make_float4(v0, v1, v2, v3);
            *reinterpret_cast<float4*>(outp + (size_t)m * (OT_ * C_) + (size_t)t * C_ + nBase) = o;
        }
    }
}

extern "C" void kernel_launch(void* const* d_in, const int* in_sizes, int n_in,
                              void* d_out, int out_size) {
    const float* x       = (const float*)d_in[0];
    const void*  lengths = d_in[1];             // int32 or int64 — detected on device
    // d_in[2] = out_lengths (constant 128, ignored)
    const float* W_ih = (const float*)d_in[3];
    const float* W_hh = (const float*)d_in[4];
    const float* b_ih = (const float*)d_in[5];
    const float* b_hh = (const float*)d_in[6];
    const float* fc1W = (const float*)d_in[7];
    const float* fc1b = (const float*)d_in[8];
    const float* fc2W = (const float*)d_in[9];
    const float* fc2b = (const float*)d_in[10];
    float* out = (float*)d_out;

    float* hbuf = nullptr;
    float* mid  = nullptr;
    cudaGetSymbolAddress((void**)&hbuf, g_h);
    cudaGetSymbolAddress((void**)&mid,  g_mid);
    float* hp[2] = { hbuf, hbuf + (size_t)B_ * H_ };

    // h0 = 0; detect lengths dtype
    zero_kernel<<<(B_ * H_ + 255) / 256, 256>>>(hp[0], B_ * H_);
    detect_len_kernel<<<1, 1>>>((const int*)lengths);

    dim3 blk(NTHR);
    dim3 grdH(B_ / BM, H_ / BN);   // 16 x 8 = 128 blocks
    dim3 grdC(B_ / BM, C_ / BN);   // 16 x 2

    int cur = 0;
    // Encoder: 512 masked recurrent steps (x@Wih fused into K-loop)
    for (int t = 0; t < T_; t++) {
        gemm_step<0><<<grdH, blk>>>(hp[cur], W_hh, x, W_ih, b_ih, b_hh,
                                    lengths, hp[cur ^ 1], t);
        cur ^= 1;
    }
    // Decoder: 128 steps of (h-update, fc1, fc2)
    for (int s = 0; s < OT_; s++) {
        gemm_step<1><<<grdH, blk>>>(hp[cur], W_hh, nullptr, nullptr, b_ih, b_hh,
                                    nullptr, hp[cur ^ 1], s);
        gemm_step<2><<<grdH, blk>>>(hp[cur ^ 1], fc1W, nullptr, nullptr, fc1b, nullptr,
                                    nullptr, mid, s);
        gemm_step<3><<<grdC, blk>>>(mid, fc2W, nullptr, nullptr, fc2b, nullptr,
                                    nullptr, out, s);
        cur ^= 1;
    }
}

// round 6
// speedup vs baseline: 2.0149x; 2.0149x over previous
#include <cuda_runtime.h>
#include <cuda_bf16.h>
#include <mma.h>
#include <cstdint>

using namespace nvcuda;

#define B_  512
#define T_  512
#define I_  128
#define H_  512
#define C_  128
#define OT_ 128

// GEMM tiling: CTA 64x32, 4 warps (2x2), warp tile 32x16, K-chunk 64
#define BM  64
#define BN  32
#define KC  64
#define LD  72      // padded bf16 leading dim for smem tiles
#define LDC 36      // padded f32 leading dim for C staging

// ---------------- device globals (allocation-free scratch) ----------------
__device__ float         g_U[(size_t)B_ * T_ * H_];                  // 512 MB
__device__ __nv_bfloat16 g_xh[(size_t)B_ * T_ * I_];
__device__ __nv_bfloat16 g_xl[(size_t)B_ * T_ * I_];
__device__ __nv_bfloat16 g_Whh_h[H_ * H_], g_Whh_l[H_ * H_];
__device__ __nv_bfloat16 g_Wih_h[H_ * I_], g_Wih_l[H_ * I_];
__device__ __nv_bfloat16 g_f1_h[H_ * H_],  g_f1_l[H_ * H_];
__device__ __nv_bfloat16 g_f2_h[C_ * H_],  g_f2_l[C_ * H_];
__device__ __nv_bfloat16 g_hh[2][B_ * H_], g_hl[2][B_ * H_];         // encoder h ping-pong
__device__ __nv_bfloat16 g_nhh[(size_t)OT_ * B_ * H_];               // decoder nh slab [s][b][h]
__device__ __nv_bfloat16 g_nhl[(size_t)OT_ * B_ * H_];
__device__ __nv_bfloat16 g_mh[(size_t)OT_ * B_ * H_];                // fc1 out slab
__device__ __nv_bfloat16 g_ml[(size_t)OT_ * B_ * H_];
__device__ float         g_bias2[H_];                                // b_ih + b_hh
__device__ int           g_len64;

// ---------------- prologue kernels ----------------
__global__ void split_kernel(const float* __restrict__ s, __nv_bfloat16* __restrict__ hi,
                             __nv_bfloat16* __restrict__ lo, long n4) {
    long i = (long)blockIdx.x * blockDim.x + threadIdx.x;
    if (i >= n4) return;
    float4 v = reinterpret_cast<const float4*>(s)[i];
    union { __nv_bfloat16 b[4]; uint2 u; } h, l;
    float a[4] = { v.x, v.y, v.z, v.w };
#pragma unroll
    for (int j = 0; j < 4; j++) {
        h.b[j] = __float2bfloat16(a[j]);
        l.b[j] = __float2bfloat16(a[j] - __bfloat162float(h.b[j]));
    }
    reinterpret_cast<uint2*>(hi)[i] = h.u;
    reinterpret_cast<uint2*>(lo)[i] = l.u;
}

__global__ void init_kernel(const float* __restrict__ b_ih, const float* __restrict__ b_hh) {
    int i = blockIdx.x * blockDim.x + threadIdx.x;
    if (i < H_) g_bias2[i] = b_ih[i] + b_hh[i];
    if (i < B_ * H_) { g_hh[0][i] = __float2bfloat16(0.f); g_hl[0][i] = __float2bfloat16(0.f); }
}

// lengths dtype sniff: int64 buffers have all odd int32 words == 0 (values < 512)
__global__ void detect_len_kernel(const int* p) {
    int is64 = 1;
    for (int i = 0; i < 32; i++)
        if (p[2 * i + 1] != 0) is64 = 0;
    g_len64 = is64;
}

// ---------------- unified WMMA GEMM step ----------------
// MODE 0: U precompute : U[b][t][:] = x_t @ Wih^T + bias2            (grid.z = t)
// MODE 1: encoder step : h' = (t < len) ? tanh(h@Whh^T + U[:,t,:]) : h
// MODE 2: decoder h    : nh_s = tanh(h@Whh^T + bias2)                -> slab
// MODE 3: fc1 batched  : mid = relu(nh@fc1W^T + fc1b)    M = OT*B
// MODE 4: fc2 batched  : out[b][s][:] = mid@fc2W^T + fc2b M = OT*B, fp32 strided
template <int MODE>
__global__ void __launch_bounds__(128)
step_kernel(const __nv_bfloat16* __restrict__ Ah, const __nv_bfloat16* __restrict__ Al, size_t lda,
            const __nv_bfloat16* __restrict__ Bh, const __nv_bfloat16* __restrict__ Bl, int ldb,
            const float* __restrict__ bias,
            const void* __restrict__ lengths,
            __nv_bfloat16* __restrict__ outh, __nv_bfloat16* __restrict__ outl,
            float* __restrict__ outf,
            int t_arg, int ns)
{
    __shared__ __align__(16) char smem[27648];
    __nv_bfloat16* sAh = reinterpret_cast<__nv_bfloat16*>(smem);            //  9216 B
    __nv_bfloat16* sAl = reinterpret_cast<__nv_bfloat16*>(smem + 9216);     //  9216 B
    __nv_bfloat16* sBh = reinterpret_cast<__nv_bfloat16*>(smem + 18432);    //  4608 B
    __nv_bfloat16* sBl = reinterpret_cast<__nv_bfloat16*>(smem + 23040);    //  4608 B
    float*         sC  = reinterpret_cast<float*>(smem);                    // reuse after mma

    const int tid = threadIdx.x, wid = tid >> 5;
    const int wy = wid >> 1, wx = wid & 1;                 // warp grid 2x2
    const int m0 = blockIdx.x * BM;
    const int n0 = blockIdx.y * BN;
    const int tt = (MODE == 0) ? (int)blockIdx.z : t_arg;
    const size_t aoff = (MODE == 0) ? (size_t)tt * I_ : 0;

    wmma::fragment<wmma::accumulator, 16, 16, 16, float> acc0, acc1;
    wmma::fill_fragment(acc0, 0.f);
    wmma::fill_fragment(acc1, 0.f);

    uint4 raH[4], raL[4], rbH[2], rbL[2];
    auto prefetch = [&](int c) {
        const int k0 = c * KC;
#pragma unroll
        for (int i = 0; i < 4; i++) {
            int id = tid + i * 128; int r = id >> 3, cc = id & 7;
            size_t g = (size_t)(m0 + r) * lda + aoff + k0 + cc * 8;
            raH[i] = *reinterpret_cast<const uint4*>(Ah + g);
            raL[i] = *reinterpret_cast<const uint4*>(Al + g);
        }
#pragma unroll
        for (int i = 0; i < 2; i++) {
            int id = tid + i * 128; int r = id >> 3, cc = id & 7;
            size_t g = (size_t)(n0 + r) * ldb + k0 + cc * 8;
            rbH[i] = *reinterpret_cast<const uint4*>(Bh + g);
            rbL[i] = *reinterpret_cast<const uint4*>(Bl + g);
        }
    };
    auto stores = [&]() {
#pragma unroll
        for (int i = 0; i < 4; i++) {
            int id = tid + i * 128; int r = id >> 3, cc = id & 7;
            *reinterpret_cast<uint4*>(sAh + r * LD + cc * 8) = raH[i];
            *reinterpret_cast<uint4*>(sAl + r * LD + cc * 8) = raL[i];
        }
#pragma unroll
        for (int i = 0; i < 2; i++) {
            int id = tid + i * 128; int r = id >> 3, cc = id & 7;
            *reinterpret_cast<uint4*>(sBh + r * LD + cc * 8) = rbH[i];
            *reinterpret_cast<uint4*>(sBl + r * LD + cc * 8) = rbL[i];
        }
    };

    prefetch(0);
    for (int s = 0; s < ns; s++) {
        stores();
        __syncthreads();
        if (s + 1 < ns) prefetch(s + 1);   // LDGs overlap the MMA phase below
#pragma unroll
        for (int ks = 0; ks < 4; ks++) {
            const int kk = ks * 16;
            wmma::fragment<wmma::matrix_a, 16, 16, 16, __nv_bfloat16, wmma::row_major> aH0, aH1, aL0, aL1;
            wmma::fragment<wmma::matrix_b, 16, 16, 16, __nv_bfloat16, wmma::col_major> bH, bL;
            wmma::load_matrix_sync(aH0, sAh + (wy * 32)      * LD + kk, LD);
            wmma::load_matrix_sync(aH1, sAh + (wy * 32 + 16) * LD + kk, LD);
            wmma::load_matrix_sync(aL0, sAl + (wy * 32)      * LD + kk, LD);
            wmma::load_matrix_sync(aL1, sAl + (wy * 32 + 16) * LD + kk, LD);
            wmma::load_matrix_sync(bH,  sBh + (wx * 16) * LD + kk, LD);
            wmma::load_matrix_sync(bL,  sBl + (wx * 16) * LD + kk, LD);
            wmma::mma_sync(acc0, aH0, bH, acc0);
            wmma::mma_sync(acc1, aH1, bH, acc1);
            wmma::mma_sync(acc0, aH0, bL, acc0);
            wmma::mma_sync(acc1, aH1, bL, acc1);
            wmma::mma_sync(acc0, aL0, bH, acc0);
            wmma::mma_sync(acc1, aL1, bH, acc1);
        }
        __syncthreads();
    }

    // Stage C in smem (overlays A tiles — safe after the final barrier)
    wmma::store_matrix_sync(sC + (wy * 32)      * LDC + wx * 16, acc0, LDC, wmma::mem_row_major);
    wmma::store_matrix_sync(sC + (wy * 32 + 16) * LDC + wx * 16, acc1, LDC, wmma::mem_row_major);
    __syncthreads();

    // Epilogue: thread -> (row r, 16-col half)
    const int r  = tid >> 1;
    const int c0 = (tid & 1) * 16;
    const int m  = m0 + r;
    const int nb = n0 + c0;

    float v[16];
#pragma unroll
    for (int j = 0; j < 4; j++)
        *reinterpret_cast<float4*>(v + j * 4) = *reinterpret_cast<const float4*>(sC + r * LDC + c0 + j * 4);

    union P8 { __nv_bfloat16 b[8]; uint4 u; };

    if constexpr (MODE == 0) {                 // U = acc + bias2 (fp32)
        float* up = g_U + ((size_t)m * T_ + tt) * H_ + nb;
#pragma unroll
        for (int j = 0; j < 16; j++) v[j] += g_bias2[nb + j];
#pragma unroll
        for (int j = 0; j < 4; j++)
            *reinterpret_cast<float4*>(up + j * 4) = *reinterpret_cast<const float4*>(v + j * 4);
    } else if constexpr (MODE == 1) {          // encoder step
        long long len = g_len64 ? ((const long long*)lengths)[m]
                                : (long long)((const int*)lengths)[m];
        __nv_bfloat16* oh = outh + (size_t)m * H_ + nb;
        __nv_bfloat16* ol = outl + (size_t)m * H_ + nb;
        if ((long long)tt < len) {
            const float* up = g_U + ((size_t)m * T_ + tt) * H_ + nb;
            P8 ph[2], pl[2];
#pragma unroll
            for (int j = 0; j < 16; j++) {
                float z = tanhf(v[j] + up[j]);
                __nv_bfloat16 h = __float2bfloat16(z);
                ph[j >> 3].b[j & 7] = h;
                pl[j >> 3].b[j & 7] = __float2bfloat16(z - __bfloat162float(h));
            }
            reinterpret_cast<uint4*>(oh)[0] = ph[0].u; reinterpret_cast<uint4*>(oh)[1] = ph[1].u;
            reinterpret_cast<uint4*>(ol)[0] = pl[0].u; reinterpret_cast<uint4*>(ol)[1] = pl[1].u;
        } else {                                // frozen row: exact bit copy
            const __nv_bfloat16* ih = Ah + (size_t)m * H_ + nb;
            const __nv_bfloat16* il = Al + (size_t)m * H_ + nb;
            reinterpret_cast<uint4*>(oh)[0] = reinterpret_cast<const uint4*>(ih)[0];
            reinterpret_cast<uint4*>(oh)[1] = reinterpret_cast<const uint4*>(ih)[1];
            reinterpret_cast<uint4*>(ol)[0] = reinterpret_cast<const uint4*>(il)[0];
            reinterpret_cast<uint4*>(ol)[1] = reinterpret_cast<const uint4*>(il)[1];
        }
    } else if constexpr (MODE == 2 || MODE == 3) {   // tanh(+bias2) / relu(+fc1b)
        const float* bv = (MODE == 2) ? g_bias2 : bias;
        __nv_bfloat16* oh = outh + (size_t)m * H_ + nb;
        __nv_bfloat16* ol = outl + (size_t)m * H_ + nb;
        P8 ph[2], pl[2];
#pragma unroll
        for (int j = 0; j < 16; j++) {
            float z = v[j] + bv[nb + j];
            z = (MODE == 2) ? tanhf(z) : fmaxf(z, 0.f);
            __nv_bfloat16 h = __float2bfloat16(z);
            ph[j >> 3].b[j & 7] = h;
            pl[j >> 3].b[j & 7] = __float2bfloat16(z - __bfloat162float(h));
        }
        reinterpret_cast<uint4*>(oh)[0] = ph[0].u; reinterpret_cast<uint4*>(oh)[1] = ph[1].u;
        reinterpret_cast<uint4*>(ol)[0] = pl[0].u; reinterpret_cast<uint4*>(ol)[1] = pl[1].u;
    } else {                                   // fc2: fp32, out[b][s][n]
        const int s = m >> 9;                  // slab row -> (s, b)
        const int b = m & 511;
        float* op = outf + ((size_t)b * OT_ + s) * C_ + nb;
#pragma unroll
        for (int j = 0; j < 16; j++) v[j] += bias[nb + j];
#pragma unroll
        for (int j = 0; j < 4; j++)
            *reinterpret_cast<float4*>(op + j * 4) = *reinterpret_cast<const float4*>(v + j * 4);
    }
}

// ---------------- host ----------------
extern "C" void kernel_launch(void* const* d_in, const int* in_sizes, int n_in,
                              void* d_out, int out_size) {
    const float* x       = (const float*)d_in[0];
    const void*  lengths = d_in[1];
    const float* W_ih = (const float*)d_in[3];
    const float* W_hh = (const float*)d_in[4];
    const float* b_ih = (const float*)d_in[5];
    const float* b_hh = (const float*)d_in[6];
    const float* fc1W = (const float*)d_in[7];
    const float* fc1b = (const float*)d_in[8];
    const float* fc2W = (const float*)d_in[9];
    const float* fc2b = (const float*)d_in[10];
    float* out = (float*)d_out;

    __nv_bfloat16 *xh, *xl, *WhhH, *WhhL, *WihH, *WihL, *f1H, *f1L, *f2H, *f2L;
    __nv_bfloat16 *hhB, *hlB, *nhh, *nhl, *mh, *ml;
    cudaGetSymbolAddress((void**)&xh,   g_xh);    cudaGetSymbolAddress((void**)&xl,   g_xl);
    cudaGetSymbolAddress((void**)&WhhH, g_Whh_h); cudaGetSymbolAddress((void**)&WhhL, g_Whh_l);
    cudaGetSymbolAddress((void**)&WihH, g_Wih_h); cudaGetSymbolAddress((void**)&WihL, g_Wih_l);
    cudaGetSymbolAddress((void**)&f1H,  g_f1_h);  cudaGetSymbolAddress((void**)&f1L,  g_f1_l);
    cudaGetSymbolAddress((void**)&f2H,  g_f2_h);  cudaGetSymbolAddress((void**)&f2L,  g_f2_l);
    cudaGetSymbolAddress((void**)&hhB,  g_hh);    cudaGetSymbolAddress((void**)&hlB,  g_hl);
    cudaGetSymbolAddress((void**)&nhh,  g_nhh);   cudaGetSymbolAddress((void**)&nhl,  g_nhl);
    cudaGetSymbolAddress((void**)&mh,   g_mh);    cudaGetSymbolAddress((void**)&ml,   g_ml);
    __nv_bfloat16* hh[2] = { hhB, hhB + (size_t)B_ * H_ };
    __nv_bfloat16* hl[2] = { hlB, hlB + (size_t)B_ * H_ };
    const size_t BH = (size_t)B_ * H_;

    // prologue: bf16 hi/lo splits; bias2; h0 = 0; lengths dtype
    auto launch_split = [](const float* s, __nv_bfloat16* h, __nv_bfloat16* l, long n) {
        long n4 = n / 4;
        split_kernel<<<(unsigned)((n4 + 255) / 256), 256>>>(s, h, l, n4);
    };
    launch_split(x,    xh,   xl,   (long)B_ * T_ * I_);
    launch_split(W_hh, WhhH, WhhL, (long)H_ * H_);
    launch_split(W_ih, WihH, WihL, (long)H_ * I_);
    launch_split(fc1W, f1H,  f1L,  (long)H_ * H_);
    launch_split(fc2W, f2H,  f2L,  (long)C_ * H_);
    init_kernel<<<(B_ * H_ + 255) / 256, 256>>>(b_ih, b_hh);
    detect_len_kernel<<<1, 1>>>((const int*)lengths);

    // U = x @ Wih^T + bias2, all (b, t) in one parallel GEMM
    step_kernel<0><<<dim3(B_ / BM, H_ / BN, T_), 128>>>(
        xh, xl, (size_t)T_ * I_, WihH, WihL, I_,
        nullptr, nullptr, nullptr, nullptr, nullptr, 0, I_ / KC);

    // encoder: 512 serial steps
    int cur = 0;
    for (int t = 0; t < T_; t++) {
        step_kernel<1><<<dim3(B_ / BM, H_ / BN), 128>>>(
            hh[cur], hl[cur], H_, WhhH, WhhL, H_,
            nullptr, lengths, hh[cur ^ 1], hl[cur ^ 1], nullptr, t, H_ / KC);
        cur ^= 1;
    }

    // decoder h-chain: 128 serial steps into the nh slab
    for (int s = 0; s < OT_; s++) {
        const __nv_bfloat16* Ah = (s == 0) ? hh[cur] : nhh + (size_t)(s - 1) * BH;
        const __nv_bfloat16* Al = (s == 0) ? hl[cur] : nhl + (size_t)(s - 1) * BH;
        step_kernel<2><<<dim3(B_ / BM, H_ / BN), 128>>>(
            Ah, Al, H_, WhhH, WhhL, H_,
            nullptr, nullptr, nhh + (size_t)s * BH, nhl + (size_t)s * BH, nullptr, s, H_ / KC);
    }

    // batched fc1 over all (s, b): M = OT*B
    step_kernel<3><<<dim3(OT_ * B_ / BM, H_ / BN), 128>>>(
        nhh, nhl, H_, f1H, f1L, H_,
        fc1b, nullptr, mh, ml, nullptr, 0, H_ / KC);

    // batched fc2: M = OT*B, N = C, fp32 strided store into d_out
    step_kernel<4><<<dim3(OT_ * B_ / BM, C_ / BN), 128>>>(
        mh, ml, H_, f2H, f2L, H_,
        fc2b, nullptr, nullptr, nullptr, out, 0, H_ / KC);
}